// round 11
// baseline (speedup 1.0000x reference)
#include <cuda_runtime.h>
#include <cuda_bf16.h>
#include <math_constants.h>

// Problem constants (fixed by the reference): B=4, H=8, S=2048, D=3
#define BATCH 4
#define HEADS 8
#define SEQ   2048
#define NGROUP (SEQ / 4)   // 512 groups of 4 keys
#define NCHUNK 32          // q-chunks per (b,h)
#define QCHUNK 64          // queries per CTA
#define NTHREADS 128       // thread = (duo 0..31 [2 queries], split 0..3)
#define GPT (NGROUP / 4)   // 128 groups per split

typedef unsigned long long u64;

__device__ __forceinline__ float ex2f(float x) {
    float y; asm("ex2.approx.f32 %0, %1;" : "=f"(y) : "f"(x)); return y;
}
__device__ __forceinline__ float rcpf(float x) {
    float y; asm("rcp.approx.f32 %0, %1;" : "=f"(y) : "f"(x)); return y;
}
__device__ __forceinline__ u64 fma2(u64 a, u64 b, u64 c) {
    u64 d; asm("fma.rn.f32x2 %0, %1, %2, %3;" : "=l"(d) : "l"(a), "l"(b), "l"(c)); return d;
}
__device__ __forceinline__ u64 mul2(u64 a, u64 b) {
    u64 d; asm("mul.rn.f32x2 %0, %1, %2;" : "=l"(d) : "l"(a), "l"(b)); return d;
}
__device__ __forceinline__ u64 add2(u64 a, u64 b) {
    u64 d; asm("add.rn.f32x2 %0, %1, %2;" : "=l"(d) : "l"(a), "l"(b)); return d;
}
__device__ __forceinline__ u64 pack2(float lo, float hi) {
    u64 d; asm("mov.b64 %0, {%1, %2};" : "=l"(d) : "f"(lo), "f"(hi)); return d;
}
__device__ __forceinline__ void unpack2(u64 v, float& lo, float& hi) {
    asm("mov.b64 {%0, %1}, %2;" : "=f"(lo), "=f"(hi) : "l"(v));
}

// exp2 on the FMA pipe: magic-number round-to-int, deg-3 poly for 2^r on
// r in [-0.5, 0.5], exponent injected via integer add on the result bits.
// 6 fma-pipe + 2 alu instrs; relative error <= ~4e-4.
__device__ __forceinline__ float ex2_poly(float t) {
    const float MAGIC = 12582912.0f;          // 1.5 * 2^23
    const float z  = t + MAGIC;               // low mantissa bits = round(t)
    const float kf = z - MAGIC;               // round(t) as float (exact)
    const float r  = t - kf;                  // r in [-0.5, 0.5]
    float p = fmaf(r, 0.0558282f, 0.2401397f);
    p = fmaf(r, p, 0.6931472f);
    p = fmaf(r, p, 1.0000000f);               // p ~= 2^r
    const int sh = __float_as_int(z) << 23;   // == k << 23 (mod 2^32)
    return __int_as_float(__float_as_int(p) + sh);
}

__global__ __launch_bounds__(NTHREADS, 8)
void attn_kernel(const float* __restrict__ x,
                 const float* __restrict__ Wq,
                 const float* __restrict__ Wk,
                 const float* __restrict__ Wv,
                 float* __restrict__ out)
{
    // x only, SoA over 4-key groups: group g = {x0[4], x1[4], x2[4]} float4s.
    // 512 * 48B = 24KB -> 8 CTAs/SM target. Reused as split-K staging.
    __shared__ float4 sX[NGROUP * 3];

    const int bh  = blockIdx.x;        // b*8 + h
    const int b   = bh >> 3;
    const int h   = bh & 7;
    const int tid = threadIdx.x;

    const float* xb = x + b * SEQ * 3;

    // Prologue: transpose-copy x into 4-key SoA packs.
    for (int g = tid; g < NGROUP; g += NTHREADS) {
        const float4* xp = reinterpret_cast<const float4*>(xb + 12 * g);
        const float4 a = xp[0], c = xp[1], d = xp[2];
        sX[3 * g + 0] = make_float4(a.x, a.w, c.z, d.y);  // x0 of keys 4g..4g+3
        sX[3 * g + 1] = make_float4(a.y, c.x, c.w, d.z);  // x1
        sX[3 * g + 2] = make_float4(a.z, c.y, d.x, d.w);  // x2
    }
    __syncthreads();

    // Decomposition: duo owns queries (qA, qB); split selects key quarter.
    const int duo   = tid & 31;
    const int split = tid >> 5;        // 0..3 (warp index -> warp-uniform)
    const int qA = blockIdx.y * QCHUNK + 2 * duo;
    const int qB = qA + 1;

    // g = cs * (x_q Wq) Wk^T  so that  t_s = g . x_s  (== scale*log2e * Q.K).
    // No row-max pass (bounded scores; softmax shift-invariant; rel_err ~4e-7).
    const float cs = 1.4426950408889634f * 0.5773502691896258f;
    const float* wqp = Wq + h * 9;
    const float* wkp = Wk + h * 9;
    float wq[9], wk[9];
#pragma unroll
    for (int i = 0; i < 9; i++) { wq[i] = __ldg(wqp + i); wk[i] = __ldg(wkp + i); }

    const float xa0 = xb[3 * qA + 0], xa1 = xb[3 * qA + 1], xa2 = xb[3 * qA + 2];
    const float xb0 = xb[3 * qB + 0], xb1 = xb[3 * qB + 1], xb2 = xb[3 * qB + 2];

    // Q[e] = sum_d xq[d] * Wq[d][e]   (Wq row-major [d][e] = wq[3d+e])
    const float QA0 = fmaf(xa2, wq[6], fmaf(xa1, wq[3], xa0 * wq[0]));
    const float QA1 = fmaf(xa2, wq[7], fmaf(xa1, wq[4], xa0 * wq[1]));
    const float QA2 = fmaf(xa2, wq[8], fmaf(xa1, wq[5], xa0 * wq[2]));
    const float QB0 = fmaf(xb2, wq[6], fmaf(xb1, wq[3], xb0 * wq[0]));
    const float QB1 = fmaf(xb2, wq[7], fmaf(xb1, wq[4], xb0 * wq[1]));
    const float QB2 = fmaf(xb2, wq[8], fmaf(xb1, wq[5], xb0 * wq[2]));
    // g[d] = cs * sum_e Q[e] * Wk[d][e]
    const float gA0 = cs * fmaf(QA2, wk[2], fmaf(QA1, wk[1], QA0 * wk[0]));
    const float gA1 = cs * fmaf(QA2, wk[5], fmaf(QA1, wk[4], QA0 * wk[3]));
    const float gA2 = cs * fmaf(QA2, wk[8], fmaf(QA1, wk[7], QA0 * wk[6]));
    const float gB0 = cs * fmaf(QB2, wk[2], fmaf(QB1, wk[1], QB0 * wk[0]));
    const float gB1 = cs * fmaf(QB2, wk[5], fmaf(QB1, wk[4], QB0 * wk[3]));
    const float gB2 = cs * fmaf(QB2, wk[8], fmaf(QB1, wk[7], QB0 * wk[6]));

    const u64 gA0p = pack2(gA0, gA0), gA1p = pack2(gA1, gA1), gA2p = pack2(gA2, gA2);
    const u64 gB0p = pack2(gB0, gB0), gB1p = pack2(gB1, gB1), gB2p = pack2(gB2, gB2);

    // Accumulators per query: den + S = sum e*x (3 dims); lo/hi key-pairs share
    // the same f32x2 accumulator.
    u64 dA = 0, sA0 = 0, sA1 = 0, sA2 = 0;
    u64 dB = 0, sB0 = 0, sB1 = 0, sB2 = 0;

    const ulonglong2* p = reinterpret_cast<const ulonglong2*>(sX) + 3 * (split * GPT);

#pragma unroll 4
    for (int it = 0; it < GPT; ++it) {
        const ulonglong2 x0 = p[0];   // dim0: pairs (k0,k1),(k2,k3)
        const ulonglong2 x1 = p[1];
        const ulonglong2 x2 = p[2];
        p += 3;

        // Query A (4 exps on MUFU)
        {
            const u64 tl = fma2(gA0p, x0.x, fma2(gA1p, x1.x, mul2(gA2p, x2.x)));
            const u64 th = fma2(gA0p, x0.y, fma2(gA1p, x1.y, mul2(gA2p, x2.y)));
            float t0, t1, t2, t3;
            unpack2(tl, t0, t1); unpack2(th, t2, t3);
            const u64 el = pack2(ex2f(t0), ex2f(t1));
            const u64 eh = pack2(ex2f(t2), ex2f(t3));
            dA  = add2(dA, el);          dA  = add2(dA, eh);
            sA0 = fma2(el, x0.x, sA0);   sA0 = fma2(eh, x0.y, sA0);
            sA1 = fma2(el, x1.x, sA1);   sA1 = fma2(eh, x1.y, sA1);
            sA2 = fma2(el, x2.x, sA2);   sA2 = fma2(eh, x2.y, sA2);
        }
        // Query B (3 exps on MUFU, 1 on the FMA pipe -> rebalances pipes:
        // MUFU floor 56.6K -> 49.5K cyc, fma 37.8K -> ~48K cyc)
        {
            const u64 tl = fma2(gB0p, x0.x, fma2(gB1p, x1.x, mul2(gB2p, x2.x)));
            const u64 th = fma2(gB0p, x0.y, fma2(gB1p, x1.y, mul2(gB2p, x2.y)));
            float t0, t1, t2, t3;
            unpack2(tl, t0, t1); unpack2(th, t2, t3);
            const u64 el = pack2(ex2f(t0), ex2f(t1));
            const u64 eh = pack2(ex2f(t2), ex2_poly(t3));
            dB  = add2(dB, el);          dB  = add2(dB, eh);
            sB0 = fma2(el, x0.x, sB0);   sB0 = fma2(eh, x0.y, sB0);
            sB1 = fma2(el, x1.x, sB1);   sB1 = fma2(eh, x1.y, sB1);
            sB2 = fma2(el, x2.x, sB2);   sB2 = fma2(eh, x2.y, sB2);
        }
    }

    // Horizontal reduce u64 pairs to scalars.
    float lo, hi;
    unpack2(dA, lo, hi);  const float denA = lo + hi;
    unpack2(sA0, lo, hi); const float SA0 = lo + hi;
    unpack2(sA1, lo, hi); const float SA1 = lo + hi;
    unpack2(sA2, lo, hi); const float SA2 = lo + hi;
    unpack2(dB, lo, hi);  const float denB = lo + hi;
    unpack2(sB0, lo, hi); const float SB0 = lo + hi;
    unpack2(sB1, lo, hi); const float SB1 = lo + hi;
    unpack2(sB2, lo, hi); const float SB2 = lo + hi;

    // Split-K merge via reused smem: splits 1..3 stage; split 0 combines.
    __syncthreads();   // all x reads done
    float4* stage = reinterpret_cast<float4*>(sX);  // [3][32][2] float4 = 3KB
    if (split != 0) {
        float4* sp = stage + ((split - 1) * 32 + duo) * 2;
        sp[0] = make_float4(denA, SA0, SA1, SA2);
        sp[1] = make_float4(denB, SB0, SB1, SB2);
    }
    __syncthreads();
    if (split == 0) {
        float4 aA = make_float4(denA, SA0, SA1, SA2);
        float4 aB = make_float4(denB, SB0, SB1, SB2);
#pragma unroll
        for (int s = 0; s < 3; s++) {
            const float4* sp = stage + (s * 32 + duo) * 2;
            const float4 vA = sp[0];
            const float4 vB = sp[1];
            aA.x += vA.x; aA.y += vA.y; aA.z += vA.z; aA.w += vA.w;
            aB.x += vB.x; aB.y += vB.y; aB.z += vB.z; aB.w += vB.w;
        }
        // ctx[e] = (sum_d S[d] * Wv[d][e]) / den   (linearity of V-projection)
        const float* wvp = Wv + h * 9;
        float wv[9];
#pragma unroll
        for (int i = 0; i < 9; i++) wv[i] = __ldg(wvp + i);

        const float invA = rcpf(aA.x);
        const float invB = rcpf(aB.x);
        const float oA0 = fmaf(aA.w, wv[6], fmaf(aA.z, wv[3], aA.y * wv[0])) * invA;
        const float oA1 = fmaf(aA.w, wv[7], fmaf(aA.z, wv[4], aA.y * wv[1])) * invA;
        const float oA2 = fmaf(aA.w, wv[8], fmaf(aA.z, wv[5], aA.y * wv[2])) * invA;
        const float oB0 = fmaf(aB.w, wv[6], fmaf(aB.z, wv[3], aB.y * wv[0])) * invB;
        const float oB1 = fmaf(aB.w, wv[7], fmaf(aB.z, wv[4], aB.y * wv[1])) * invB;
        const float oB2 = fmaf(aB.w, wv[8], fmaf(aB.z, wv[5], aB.y * wv[2])) * invB;

        const int base = (bh * SEQ + qA) * 3;   // 6 consecutive floats, 8B-aligned
        const int dup  = BATCH * HEADS * SEQ * 3;
        float2* o1 = reinterpret_cast<float2*>(out + base);
        float2* o2 = reinterpret_cast<float2*>(out + dup + base);
        o1[0] = make_float2(oA0, oA1);
        o1[1] = make_float2(oA2, oB0);
        o1[2] = make_float2(oB1, oB2);
        o2[0] = make_float2(oA0, oA1);
        o2[1] = make_float2(oA2, oB0);
        o2[2] = make_float2(oB1, oB2);
    }
}

extern "C" void kernel_launch(void* const* d_in, const int* in_sizes, int n_in,
                              void* d_out, int out_size)
{
    const float* x  = (const float*)d_in[0];
    const float* Wq = (const float*)d_in[1];
    const float* Wk = (const float*)d_in[2];
    const float* Wv = (const float*)d_in[3];
    float* out = (float*)d_out;

    dim3 grid(BATCH * HEADS, NCHUNK);   // 32 x 32 = 1024 CTAs
    attn_kernel<<<grid, NTHREADS>>>(x, Wq, Wk, Wv, out);
}

// round 12
// speedup vs baseline: 1.0541x; 1.0541x over previous
#include <cuda_runtime.h>
#include <cuda_bf16.h>
#include <math_constants.h>

// Problem constants (fixed by the reference): B=4, H=8, S=2048, D=3
#define BATCH 4
#define HEADS 8
#define SEQ   2048
#define NGROUP (SEQ / 4)   // 512 groups of 4 keys
#define NCHUNK 32          // q-chunks per (b,h)
#define QCHUNK 64          // queries per CTA
#define NTHREADS 256       // thread = (duo 0..31 [2 queries], split 0..7)
#define NSPLIT 8
#define GPT (NGROUP / NSPLIT)  // 64 groups per split

typedef unsigned long long u64;

__device__ __forceinline__ float ex2f(float x) {
    float y; asm("ex2.approx.f32 %0, %1;" : "=f"(y) : "f"(x)); return y;
}
__device__ __forceinline__ float rcpf(float x) {
    float y; asm("rcp.approx.f32 %0, %1;" : "=f"(y) : "f"(x)); return y;
}
__device__ __forceinline__ u64 fma2(u64 a, u64 b, u64 c) {
    u64 d; asm("fma.rn.f32x2 %0, %1, %2, %3;" : "=l"(d) : "l"(a), "l"(b), "l"(c)); return d;
}
__device__ __forceinline__ u64 mul2(u64 a, u64 b) {
    u64 d; asm("mul.rn.f32x2 %0, %1, %2;" : "=l"(d) : "l"(a), "l"(b)); return d;
}
__device__ __forceinline__ u64 add2(u64 a, u64 b) {
    u64 d; asm("add.rn.f32x2 %0, %1, %2;" : "=l"(d) : "l"(a), "l"(b)); return d;
}
__device__ __forceinline__ u64 pack2(float lo, float hi) {
    u64 d; asm("mov.b64 %0, {%1, %2};" : "=l"(d) : "f"(lo), "f"(hi)); return d;
}
__device__ __forceinline__ void unpack2(u64 v, float& lo, float& hi) {
    asm("mov.b64 {%0, %1}, %2;" : "=f"(lo), "=f"(hi) : "l"(v));
}

__global__ __launch_bounds__(NTHREADS, 4)
void attn_kernel(const float* __restrict__ x,
                 const float* __restrict__ Wq,
                 const float* __restrict__ Wk,
                 const float* __restrict__ Wv,
                 float* __restrict__ out)
{
    // x only, SoA over 4-key groups: group g = {x0[4], x1[4], x2[4]} float4s.
    // 512 * 48B = 24KB. Reused as split-K staging.
    __shared__ float4 sX[NGROUP * 3];

    const int bh  = blockIdx.x;        // b*8 + h
    const int b   = bh >> 3;
    const int h   = bh & 7;
    const int tid = threadIdx.x;

    const float* xb = x + b * SEQ * 3;

    // Prologue: transpose-copy x into 4-key SoA packs (2 groups per thread).
    for (int g = tid; g < NGROUP; g += NTHREADS) {
        const float4* xp = reinterpret_cast<const float4*>(xb + 12 * g);
        const float4 a = xp[0], c = xp[1], d = xp[2];
        sX[3 * g + 0] = make_float4(a.x, a.w, c.z, d.y);  // x0 of keys 4g..4g+3
        sX[3 * g + 1] = make_float4(a.y, c.x, c.w, d.z);  // x1
        sX[3 * g + 2] = make_float4(a.z, c.y, d.x, d.w);  // x2
    }
    __syncthreads();

    // Decomposition: duo owns queries (qA, qB); split selects key eighth.
    const int duo   = tid & 31;
    const int split = tid >> 5;        // 0..7 (warp index -> warp-uniform)
    const int qA = blockIdx.y * QCHUNK + 2 * duo;
    const int qB = qA + 1;

    // g = cs * (x_q Wq) Wk^T  so that  t_s = g . x_s  (== scale*log2e * Q.K).
    // No row-max pass (bounded scores; softmax shift-invariant; rel_err ~4e-7).
    const float cs = 1.4426950408889634f * 0.5773502691896258f;
    const float* wqp = Wq + h * 9;
    const float* wkp = Wk + h * 9;
    float wq[9], wk[9];
#pragma unroll
    for (int i = 0; i < 9; i++) { wq[i] = __ldg(wqp + i); wk[i] = __ldg(wkp + i); }

    const float xa0 = xb[3 * qA + 0], xa1 = xb[3 * qA + 1], xa2 = xb[3 * qA + 2];
    const float xb0 = xb[3 * qB + 0], xb1 = xb[3 * qB + 1], xb2 = xb[3 * qB + 2];

    // Q[e] = sum_d xq[d] * Wq[d][e]   (Wq row-major [d][e] = wq[3d+e])
    const float QA0 = fmaf(xa2, wq[6], fmaf(xa1, wq[3], xa0 * wq[0]));
    const float QA1 = fmaf(xa2, wq[7], fmaf(xa1, wq[4], xa0 * wq[1]));
    const float QA2 = fmaf(xa2, wq[8], fmaf(xa1, wq[5], xa0 * wq[2]));
    const float QB0 = fmaf(xb2, wq[6], fmaf(xb1, wq[3], xb0 * wq[0]));
    const float QB1 = fmaf(xb2, wq[7], fmaf(xb1, wq[4], xb0 * wq[1]));
    const float QB2 = fmaf(xb2, wq[8], fmaf(xb1, wq[5], xb0 * wq[2]));
    // g[d] = cs * sum_e Q[e] * Wk[d][e]
    const float gA0 = cs * fmaf(QA2, wk[2], fmaf(QA1, wk[1], QA0 * wk[0]));
    const float gA1 = cs * fmaf(QA2, wk[5], fmaf(QA1, wk[4], QA0 * wk[3]));
    const float gA2 = cs * fmaf(QA2, wk[8], fmaf(QA1, wk[7], QA0 * wk[6]));
    const float gB0 = cs * fmaf(QB2, wk[2], fmaf(QB1, wk[1], QB0 * wk[0]));
    const float gB1 = cs * fmaf(QB2, wk[5], fmaf(QB1, wk[4], QB0 * wk[3]));
    const float gB2 = cs * fmaf(QB2, wk[8], fmaf(QB1, wk[7], QB0 * wk[6]));

    const u64 gA0p = pack2(gA0, gA0), gA1p = pack2(gA1, gA1), gA2p = pack2(gA2, gA2);
    const u64 gB0p = pack2(gB0, gB0), gB1p = pack2(gB1, gB1), gB2p = pack2(gB2, gB2);

    // Accumulators per query: den + S = sum e*x (3 dims); lo/hi key-pairs share
    // the same f32x2 accumulator.
    u64 dA = 0, sA0 = 0, sA1 = 0, sA2 = 0;
    u64 dB = 0, sB0 = 0, sB1 = 0, sB2 = 0;

    const ulonglong2* p = reinterpret_cast<const ulonglong2*>(sX) + 3 * (split * GPT);

#pragma unroll 4
    for (int it = 0; it < GPT; ++it) {
        const ulonglong2 x0 = p[0];   // dim0: pairs (k0,k1),(k2,k3)
        const ulonglong2 x1 = p[1];
        const ulonglong2 x2 = p[2];
        p += 3;

        // Query A
        {
            const u64 tl = fma2(gA0p, x0.x, fma2(gA1p, x1.x, mul2(gA2p, x2.x)));
            const u64 th = fma2(gA0p, x0.y, fma2(gA1p, x1.y, mul2(gA2p, x2.y)));
            float t0, t1, t2, t3;
            unpack2(tl, t0, t1); unpack2(th, t2, t3);
            const u64 el = pack2(ex2f(t0), ex2f(t1));
            const u64 eh = pack2(ex2f(t2), ex2f(t3));
            dA  = add2(dA, el);          dA  = add2(dA, eh);
            sA0 = fma2(el, x0.x, sA0);   sA0 = fma2(eh, x0.y, sA0);
            sA1 = fma2(el, x1.x, sA1);   sA1 = fma2(eh, x1.y, sA1);
            sA2 = fma2(el, x2.x, sA2);   sA2 = fma2(eh, x2.y, sA2);
        }
        // Query B
        {
            const u64 tl = fma2(gB0p, x0.x, fma2(gB1p, x1.x, mul2(gB2p, x2.x)));
            const u64 th = fma2(gB0p, x0.y, fma2(gB1p, x1.y, mul2(gB2p, x2.y)));
            float t0, t1, t2, t3;
            unpack2(tl, t0, t1); unpack2(th, t2, t3);
            const u64 el = pack2(ex2f(t0), ex2f(t1));
            const u64 eh = pack2(ex2f(t2), ex2f(t3));
            dB  = add2(dB, el);          dB  = add2(dB, eh);
            sB0 = fma2(el, x0.x, sB0);   sB0 = fma2(eh, x0.y, sB0);
            sB1 = fma2(el, x1.x, sB1);   sB1 = fma2(eh, x1.y, sB1);
            sB2 = fma2(el, x2.x, sB2);   sB2 = fma2(eh, x2.y, sB2);
        }
    }

    // Horizontal reduce u64 pairs to scalars.
    float lo, hi;
    unpack2(dA, lo, hi);  const float denA = lo + hi;
    unpack2(sA0, lo, hi); const float SA0 = lo + hi;
    unpack2(sA1, lo, hi); const float SA1 = lo + hi;
    unpack2(sA2, lo, hi); const float SA2 = lo + hi;
    unpack2(dB, lo, hi);  const float denB = lo + hi;
    unpack2(sB0, lo, hi); const float SB0 = lo + hi;
    unpack2(sB1, lo, hi); const float SB1 = lo + hi;
    unpack2(sB2, lo, hi); const float SB2 = lo + hi;

    // Split-K merge via reused smem: splits 1..7 stage; split 0 combines.
    __syncthreads();   // all x reads done
    float4* stage = reinterpret_cast<float4*>(sX);  // [7][32][2] float4 = 7KB
    if (split != 0) {
        float4* sp = stage + ((split - 1) * 32 + duo) * 2;
        sp[0] = make_float4(denA, SA0, SA1, SA2);
        sp[1] = make_float4(denB, SB0, SB1, SB2);
    }
    __syncthreads();
    if (split == 0) {
        float4 aA = make_float4(denA, SA0, SA1, SA2);
        float4 aB = make_float4(denB, SB0, SB1, SB2);
#pragma unroll
        for (int s = 0; s < 7; s++) {
            const float4* sp = stage + (s * 32 + duo) * 2;
            const float4 vA = sp[0];
            const float4 vB = sp[1];
            aA.x += vA.x; aA.y += vA.y; aA.z += vA.z; aA.w += vA.w;
            aB.x += vB.x; aB.y += vB.y; aB.z += vB.z; aB.w += vB.w;
        }
        // ctx[e] = (sum_d S[d] * Wv[d][e]) / den   (linearity of V-projection)
        const float* wvp = Wv + h * 9;
        float wv[9];
#pragma unroll
        for (int i = 0; i < 9; i++) wv[i] = __ldg(wvp + i);

        const float invA = rcpf(aA.x);
        const float invB = rcpf(aB.x);
        const float oA0 = fmaf(aA.w, wv[6], fmaf(aA.z, wv[3], aA.y * wv[0])) * invA;
        const float oA1 = fmaf(aA.w, wv[7], fmaf(aA.z, wv[4], aA.y * wv[1])) * invA;
        const float oA2 = fmaf(aA.w, wv[8], fmaf(aA.z, wv[5], aA.y * wv[2])) * invA;
        const float oB0 = fmaf(aB.w, wv[6], fmaf(aB.z, wv[3], aB.y * wv[0])) * invB;
        const float oB1 = fmaf(aB.w, wv[7], fmaf(aB.z, wv[4], aB.y * wv[1])) * invB;
        const float oB2 = fmaf(aB.w, wv[8], fmaf(aB.z, wv[5], aB.y * wv[2])) * invB;

        const int base = (bh * SEQ + qA) * 3;   // 6 consecutive floats, 8B-aligned
        const int dup  = BATCH * HEADS * SEQ * 3;
        float2* o1 = reinterpret_cast<float2*>(out + base);
        float2* o2 = reinterpret_cast<float2*>(out + dup + base);
        o1[0] = make_float2(oA0, oA1);
        o1[1] = make_float2(oA2, oB0);
        o1[2] = make_float2(oB1, oB2);
        o2[0] = make_float2(oA0, oA1);
        o2[1] = make_float2(oA2, oB0);
        o2[2] = make_float2(oB1, oB2);
    }
}

extern "C" void kernel_launch(void* const* d_in, const int* in_sizes, int n_in,
                              void* d_out, int out_size)
{
    const float* x  = (const float*)d_in[0];
    const float* Wq = (const float*)d_in[1];
    const float* Wk = (const float*)d_in[2];
    const float* Wv = (const float*)d_in[3];
    float* out = (float*)d_out;

    dim3 grid(BATCH * HEADS, NCHUNK);   // 32 x 32 = 1024 CTAs, 4/SM resident
    attn_kernel<<<grid, NTHREADS>>>(x, Wq, Wk, Wv, out);
}